// round 13
// baseline (speedup 1.0000x reference)
#include <cuda_runtime.h>
#include <math.h>

#define F_EPS 1e-9f
#define F_INF __int_as_float(0x7f800000)
#define FULLM 0xffffffffu

constexpr int MD = 10;
constexpr int H  = 48;
constexpr int NF = 60;
constexpr int CS = 44;              // 4-row chunk stride (floats); 44*4=176 B, 16B-aligned
constexpr int CHUNK_F  = 32 * CS;   // 1408 floats per buffer
constexpr int OFF_MINI = 4 * CHUNK_F;        // after 2 warps x 2 buffers
constexpr int OFF_FT   = OFF_MINI + 320;
constexpr int SMEM_F   = OFF_FT + NF * 32;   // 30.75 KB

// combine-buffer (ALIASED onto warp0's chunk buffers; all writes occur after
// warp0's buffers are dead, reads after __syncthreads):
// 0..9 us | 10 csum | 11 cssum | 12 path | 13 fsum | 14 shsum | 15 dmsq
// 16 uss | 17 cossum | 18 cossq | 19 dirch | 20 maxdm | 21 negmn | 22 maxcs
// 23 tdpA | 24..33 vA | 34..43 u23

__device__ __forceinline__ unsigned long long pk2(float a, float b) {
    unsigned long long r;
    asm("mov.b64 %0, {%1, %2};" : "=l"(r) : "f"(a), "f"(b));
    return r;
}
__device__ __forceinline__ void upk2(unsigned long long v, float& a, float& b) {
    asm("mov.b64 {%0, %1}, %2;" : "=f"(a), "=f"(b) : "l"(v));
}
__device__ __forceinline__ unsigned long long fma2(unsigned long long a,
                                                   unsigned long long b,
                                                   unsigned long long c) {
    unsigned long long d;
    asm("fma.rn.f32x2 %0, %1, %2, %3;" : "=l"(d) : "l"(a), "l"(b), "l"(c));
    return d;
}
__device__ __forceinline__ unsigned smem_u32(const void* p) {
    return (unsigned)__cvta_generic_to_shared(p);
}
__device__ __forceinline__ void cpa16(unsigned d, const void* s) {
    asm volatile("cp.async.ca.shared.global [%0], [%1], 16;" :: "r"(d), "l"(s) : "memory");
}
#define CP_COMMIT() asm volatile("cp.async.commit_group;" ::: "memory")
#define CP_WAIT(n)  asm volatile("cp.async.wait_group %0;" :: "n"(n) : "memory")

// block = 64 threads = one warp-PAIR handling 32 trajectories (lane = traj)
__global__ void __launch_bounds__(64, 7)
fused_kernel(const float* __restrict__ coords, const int* __restrict__ lengths,
             const float* __restrict__ Wg, const float* __restrict__ bg,
             const float* __restrict__ lnwg, const float* __restrict__ lnbg,
             float* __restrict__ out, int B)
{
    __shared__ alignas(16) float S[SMEM_F];

    const int h    = threadIdx.x >> 5;      // 0: rows 0-24, 1: rows 24-47
    const int lane = threadIdx.x & 31;
    const int t0   = blockIdx.x * 32;
    if (t0 >= B) return;

    float* bufs0  = S + h * 2 * CHUNK_F;
    float* s_mini = S + OFF_MINI;
    float* sfT    = S + OFF_FT;
    float* s_comb = S;                      // aliased over warp0's buffers

    const int  traj = t0 + lane;
    const bool vt   = traj < B;
    const int  n    = vt ? __ldg(lengths + traj) : 4;
    const int  m    = n - 1;
    const int  half = m >> 1;
    const float nf  = (float)n;
    const float mf  = (float)m;
    const int  base = h * 24;

    float csum = 0.f, cssum = 0.f, path = 0.f, fsum = 0.f, shsum = 0.f;
    float dmsq = 0.f, uss = 0.f, cossum = 0.f, cossq = 0.f, dirch = 0.f, tdpA = 0.f;
    float maxdm = -F_INF, negmn = -F_INF, maxcs = -F_INF;
    float us[MD], f0[MD], prev[MD], dprev[MD];
    float d24s[MD], vBs[MD], rin24s = 0.f;
#pragma unroll
    for (int k = 0; k < MD; k++) { us[k] = 0.f; dprev[k] = 0.f; d24s[k] = 0.f; vBs[k] = 0.f; }
    float rinprev = 0.f;

    auto body = [&](int gr, const float* row) {
        if (gr == base) {
#pragma unroll
            for (int k = 0; k < MD; k++) f0[k] = row[k];
        } else {
            float d[MD];
            float ssa = 0.f, ssb = 0.f;
#pragma unroll
            for (int k = 0; k < 5; k++)  { d[k] = row[k] - prev[k]; ssa = fmaf(d[k], d[k], ssa); }
#pragma unroll
            for (int k = 5; k < MD; k++) { d[k] = row[k] - prev[k]; ssb = fmaf(d[k], d[k], ssb); }
            float ss   = ssa + ssb;
            float ssc  = fmaxf(ss, 1e-30f);
            float rs   = rsqrtf(ssc);
            float dmag = (ss > 0.f) ? ssc * rs : 0.f;
            float rin  = (dmag > 1e-8f) ? rs : 1e8f;
            float dot  = 0.f;
#pragma unroll
            for (int k = 0; k < MD; k++) dot = fmaf(d[k], dprev[k], dot);
            float cosv = dot * rin * rinprev;
            const bool rv = gr < n;
            if (rv) {
                const int i = gr - 1;
                path += dmag;
                dmsq += ss;
                if (i <= half) fsum  += dmag;
                if (i >= half) shsum += dmag;
                maxdm = fmaxf(maxdm, dmag);
                uss   = fmaf(ss * rin, rin, uss);
#pragma unroll
                for (int k = 0; k < MD; k++) us[k] = fmaf(d[k], rin, us[k]);
                if (gr >= base + 2) {
                    cossum += cosv;
                    cossq   = fmaf(cosv, cosv, cossq);
                    negmn   = fmaxf(negmn, -cosv);
                    maxcs   = fmaxf(maxcs, cosv);
                    if (cosv < 0.f) dirch += 1.f;
                }
                if (gr == n - 1) {
                    if (h == 0) {
                        float t = 0.f;
#pragma unroll
                        for (int k = 0; k < MD; k++) { float dd = row[k] - f0[k]; t = fmaf(dd, dd, t); }
                        tdpA = t;
                    } else {
#pragma unroll
                        for (int k = 0; k < MD; k++) vBs[k] = row[k] - f0[k];
                    }
                }
                if (i < 3) {
#pragma unroll
                    for (int k = 0; k < MD; k++) sfT[(21 + i * MD + k) * 32 + lane] = d[k];
                }
            }
            if (gr >= 2 && gr <= 10)
                sfT[(51 + gr - 2) * 32 + lane] = rv ? (1.f - cosv) : 0.f;
            if (h == 1 && gr == 25) {
#pragma unroll
                for (int k = 0; k < MD; k++) d24s[k] = d[k];
                rin24s = rin;
            }
            if (h == 0 && gr == 24) {
                // warp0 buffers are dead here: safe to write aliased comb
#pragma unroll
                for (int k = 0; k < MD; k++) {
                    s_comb[(24 + k) * 32 + lane] = row[k] - f0[k];   // vA
                    s_comb[(34 + k) * 32 + lane] = d[k] * rin;       // u23
                }
            }
#pragma unroll
            for (int k = 0; k < MD; k++) dprev[k] = d[k];
            rinprev = rin;
        }
        const bool own = (h == 1) || (gr < 24);   // row-level ownership (row 24 -> warp 1)
        if (gr < n && own) {
#pragma unroll
            for (int k = 0; k < MD; k++) { csum += row[k]; cssum = fmaf(row[k], row[k], cssum); }
        }
#pragma unroll
        for (int k = 0; k < MD; k++) prev[k] = row[k];
    };

    // ---- double-buffered cp.async walk: 24 rows in 6 chunks of 4 ----
    const float4* cb4 = (const float4*)coords;
    auto stage = [&](int c, float* dst) {
#pragma unroll
        for (int u = 0; u < 10; u++) {
            int j = u * 32 + lane, tt = j / 10, wi = j - tt * 10;
            int g = t0 + tt; if (g > B - 1) g = B - 1;
            cpa16(smem_u32(dst + tt * CS + wi * 4),
                  cb4 + (size_t)g * 120 + h * 60 + c * 10 + wi);
        }
        CP_COMMIT();
    };

    stage(0, bufs0);
    for (int c = 0; c < 6; c++) {
        float* cur = bufs0 + (c & 1) * CHUNK_F;
        if (c < 5) {
            stage(c + 1, bufs0 + ((c + 1) & 1) * CHUNK_F);
            CP_WAIT(1);
        } else {
            CP_WAIT(0);
        }
        __syncwarp();
#pragma unroll
        for (int r8 = 0; r8 < 4; r8++) {
            const int gr = base + c * 4 + r8;
            float row[MD];
            const float2* rp = (const float2*)(cur + lane * CS + r8 * MD);
#pragma unroll
            for (int k = 0; k < 5; k++) { float2 v = rp[k]; row[2*k] = v.x; row[2*k+1] = v.y; }
            body(gr, row);
        }
        __syncwarp();
    }

    // ---- warp 0 extra step: row 24 (delta 23, cos 22, vA, u23) ----
    if (h == 0) {
#pragma unroll
        for (int u = 0; u < 5; u++) {
            int j = u * 32 + lane, tt = j / 5, wi = j - tt * 5;
            int g = t0 + tt; if (g > B - 1) g = B - 1;
            float2 v = ((const float2*)coords)[(size_t)g * 240 + 120 + wi];
            s_mini[tt * 10 + wi * 2]     = v.x;
            s_mini[tt * 10 + wi * 2 + 1] = v.y;
        }
        __syncwarp();
        float row[MD];
#pragma unroll
        for (int k = 0; k < MD; k++) row[k] = s_mini[lane * 10 + k];
        body(24, row);

        // publish warp-0 partials (buffers dead -> aliased comb is safe)
#pragma unroll
        for (int k = 0; k < MD; k++) s_comb[k * 32 + lane] = us[k];
        s_comb[10*32+lane] = csum;   s_comb[11*32+lane] = cssum;
        s_comb[12*32+lane] = path;   s_comb[13*32+lane] = fsum;
        s_comb[14*32+lane] = shsum;  s_comb[15*32+lane] = dmsq;
        s_comb[16*32+lane] = uss;    s_comb[17*32+lane] = cossum;
        s_comb[18*32+lane] = cossq;  s_comb[19*32+lane] = dirch;
        s_comb[20*32+lane] = maxdm;  s_comb[21*32+lane] = negmn;
        s_comb[22*32+lane] = maxcs;  s_comb[23*32+lane] = tdpA;
    }
    __syncthreads();

    // ---- warp 1 merges, stitches cross terms, runs epilogue ----
    if (h == 1) {
#pragma unroll
        for (int k = 0; k < MD; k++) us[k] += s_comb[k * 32 + lane];
        csum   += s_comb[10*32+lane];  cssum  += s_comb[11*32+lane];
        path   += s_comb[12*32+lane];  fsum   += s_comb[13*32+lane];
        shsum  += s_comb[14*32+lane];  dmsq   += s_comb[15*32+lane];
        uss    += s_comb[16*32+lane];  cossum += s_comb[17*32+lane];
        cossq  += s_comb[18*32+lane];  dirch  += s_comb[19*32+lane];
        maxdm = fmaxf(maxdm, s_comb[20*32+lane]);
        negmn = fmaxf(negmn, s_comb[21*32+lane]);
        maxcs = fmaxf(maxcs, s_comb[22*32+lane]);

        float tdp;
        if (n >= 26) {
            float t = 0.f, dot = 0.f;
#pragma unroll
            for (int k = 0; k < MD; k++) {
                float dd = s_comb[(24+k)*32+lane] + vBs[k];              // vA + vB
                t = fmaf(dd, dd, t);
                dot = fmaf(s_comb[(34+k)*32+lane], d24s[k], dot);        // u23 . d24
            }
            tdp = t;
            float c23 = dot * rin24s;
            cossum += c23;
            cossq   = fmaf(c23, c23, cossq);
            negmn   = fmaxf(negmn, -c23);
            maxcs   = fmaxf(maxcs, c23);
            if (c23 < 0.f) dirch += 1.f;
        } else {
            tdp = s_comb[23*32+lane];
        }

        float s_mincs = -negmn;
        float total_disp = (tdp > 0.f) ? sqrtf(fmaxf(tdp, 1e-30f)) : 0.f;
        float disp_ratio = __fdividef(total_disp, path + F_EPS);
        float loop_score = 1.f - disp_ratio;
        float ncf  = (float)(n - 2);
        float rncf = __fdividef(1.f, ncf);
        float mean_cos  = cossum * rncf;
        float mean_curv = 1.f - mean_cos;
        float max_curv  = 1.0f - s_mincs;
        float cvsq      = ncf - 2.0f * cossum + cossq;
        float curv_var  = (cvsq - ncf * mean_curv * mean_curv)
                          * __fdividef(1.f, fmaxf(ncf - 1.f, 1.f));
        float std_curv  = (ncf > 1.f) ? sqrtf(fmaxf(curv_var, 1e-30f)) : 0.f;
        float curv_range = maxcs - s_mincs;
        float dir_chg   = dirch * rncf;
        float fh = fsum  * __fdividef(1.f, (float)(half + 1));
        float sh = shsum * __fdividef(1.f, (float)(m - half));
        float conv = __fdividef(fh - sh, fh + F_EPS);
        float nsq = 0.f;
#pragma unroll
        for (int k = 0; k < MD; k++) nsq = fmaf(us[k], us[k], nsq);
        float npairs = mf * (mf - 1.f) * 0.5f;
        float par = 0.5f * (nsq - uss) * __fdividef(1.f, fmaxf(npairs, 1.f));
        float mean_dm = path * __fdividef(1.f, mf);
        float dm_var  = (dmsq - mf * mean_dm * mean_dm)
                        * __fdividef(1.f, fmaxf(mf - 1.f, 1.f));
        float std_dm  = sqrtf(fmaxf(dm_var, 1e-30f));
        float jump = (mean_dm > F_EPS) ? __fdividef(maxdm, mean_dm) : 1.f;
        float cnt  = nf * (float)MD;
        float mc   = csum * __fdividef(1.f, cnt);
        float cvar = (cssum - cnt * mc * mc) * __fdividef(1.f, cnt - 1.f);
        float stdc = sqrtf(fmaxf(cvar, 1e-30f));

        sfT[ 0*32+lane] = total_disp;  sfT[ 1*32+lane] = path;
        sfT[ 2*32+lane] = disp_ratio;  sfT[ 3*32+lane] = nf * 0.1f;
        sfT[ 4*32+lane] = mean_curv;   sfT[ 5*32+lane] = max_curv;
        sfT[ 6*32+lane] = std_curv;    sfT[ 7*32+lane] = curv_range;
        sfT[ 8*32+lane] = mean_cos;    sfT[ 9*32+lane] = s_mincs;
        sfT[10*32+lane] = dir_chg;     sfT[11*32+lane] = disp_ratio;
        sfT[12*32+lane] = loop_score;  sfT[13*32+lane] = conv;
        sfT[14*32+lane] = par;         sfT[15*32+lane] = jump;
        sfT[16*32+lane] = -conv;       sfT[17*32+lane] = mean_dm;
        sfT[18*32+lane] = std_dm;      sfT[19*32+lane] = mc;
        sfT[20*32+lane] = stdc;
    }
    __syncthreads();

    // ---- GEMM + LN + GELU: warp h does 16 rows; lane = (rowq, colg), 4 rows x 6 cols ----
    {
        const int colg = lane & 7;
        const int rowq = lane >> 3;
        const int colb = colg * 6;
        const int rbase = h * 16 + rowq * 4;

        unsigned long long acc[4][3];
        {
            float2 bb0 = __ldg((const float2*)(bg + colb));
            float2 bb1 = __ldg((const float2*)(bg + colb + 2));
            float2 bb2 = __ldg((const float2*)(bg + colb + 4));
            unsigned long long b0 = pk2(bb0.x, bb0.y);
            unsigned long long b1 = pk2(bb1.x, bb1.y);
            unsigned long long b2 = pk2(bb2.x, bb2.y);
#pragma unroll
            for (int rr = 0; rr < 4; rr++) { acc[rr][0] = b0; acc[rr][1] = b1; acc[rr][2] = b2; }
        }

#pragma unroll 6
        for (int f = 0; f < NF; f++) {
            float2 wa = __ldg((const float2*)(Wg + f * H + colb));
            float2 wb = __ldg((const float2*)(Wg + f * H + colb + 2));
            float2 wc = __ldg((const float2*)(Wg + f * H + colb + 4));
            unsigned long long w0 = pk2(wa.x, wa.y);
            unsigned long long w1 = pk2(wb.x, wb.y);
            unsigned long long w2 = pk2(wc.x, wc.y);
            float4 fv = *(const float4*)(sfT + f * 32 + rbase);
            float fvv[4] = {fv.x, fv.y, fv.z, fv.w};
#pragma unroll
            for (int rr = 0; rr < 4; rr++) {
                unsigned long long fp = pk2(fvv[rr], fvv[rr]);
                acc[rr][0] = fma2(fp, w0, acc[rr][0]);
                acc[rr][1] = fma2(fp, w1, acc[rr][1]);
                acc[rr][2] = fma2(fp, w2, acc[rr][2]);
            }
        }

        float lw[6], lb[6];
        {
            float2 a0 = __ldg((const float2*)(lnwg + colb));
            float2 a1 = __ldg((const float2*)(lnwg + colb + 2));
            float2 a2 = __ldg((const float2*)(lnwg + colb + 4));
            float2 c0 = __ldg((const float2*)(lnbg + colb));
            float2 c1 = __ldg((const float2*)(lnbg + colb + 2));
            float2 c2 = __ldg((const float2*)(lnbg + colb + 4));
            lw[0]=a0.x; lw[1]=a0.y; lw[2]=a1.x; lw[3]=a1.y; lw[4]=a2.x; lw[5]=a2.y;
            lb[0]=c0.x; lb[1]=c0.y; lb[2]=c1.x; lb[3]=c1.y; lb[4]=c2.x; lb[5]=c2.y;
        }

#pragma unroll
        for (int rr = 0; rr < 4; rr++) {
            float x[6];
            upk2(acc[rr][0], x[0], x[1]);
            upk2(acc[rr][1], x[2], x[3]);
            upk2(acc[rr][2], x[4], x[5]);
            float s = 0.f, sq = 0.f;
#pragma unroll
            for (int c = 0; c < 6; c++) { s += x[c]; sq = fmaf(x[c], x[c], sq); }
#pragma unroll
            for (int o = 1; o < 8; o <<= 1) {
                s  += __shfl_xor_sync(FULLM, s,  o);
                sq += __shfl_xor_sync(FULLM, sq, o);
            }
            float mu  = s * (1.0f / 48.0f);
            float var = sq * (1.0f / 48.0f) - mu * mu;
            float inv = rsqrtf(var + 1e-5f);

            int trow = t0 + rbase + rr;
            if (trow < B) {
                float y[6];
#pragma unroll
                for (int c = 0; c < 6; c++) {
                    float v = (x[c] - mu) * inv * lw[c] + lb[c];
                    y[c] = v * normcdff(v);     // exact GELU
                }
                float* op = out + (size_t)trow * H + colb;
                *(float2*)(op + 0) = make_float2(y[0], y[1]);
                *(float2*)(op + 2) = make_float2(y[2], y[3]);
                *(float2*)(op + 4) = make_float2(y[4], y[5]);
            }
        }
    }
}

extern "C" void kernel_launch(void* const* d_in, const int* in_sizes, int n_in,
                              void* d_out, int out_size) {
    const float* coords  = (const float*)d_in[0];
    const int*   lengths = (const int*)d_in[1];
    const float* W       = (const float*)d_in[2];
    const float* b       = (const float*)d_in[3];
    const float* lnw     = (const float*)d_in[4];
    const float* lnb     = (const float*)d_in[5];
    float* out = (float*)d_out;

    int B = in_sizes[1];
    int grid = (B + 31) / 32;
    fused_kernel<<<grid, 64>>>(coords, lengths, W, b, lnw, lnb, out, B);
}

// round 15
// speedup vs baseline: 1.0077x; 1.0077x over previous
#include <cuda_runtime.h>
#include <math.h>

#define F_EPS 1e-9f
#define F_INF __int_as_float(0x7f800000)
#define FULLM 0xffffffffu

constexpr int MD = 10;
constexpr int H  = 48;
constexpr int NF = 60;
constexpr int CS = 42;                    // chunk stride (floats) per trajectory
constexpr int CHUNK_F  = 32 * CS;         // 1344 floats per warp buffer
constexpr int OFF_MINI = 4 * CHUNK_F;     // 3 minis x 320 floats
constexpr int OFF_FT   = OFF_MINI + 3 * 320;
constexpr int SMEM_F   = OFF_FT + NF * 32;   // 8256 floats = 32.25 KB
constexpr int NSLOT = 54;                 // combine slots per publishing warp

// comb (ALIASED on the 4 chunk buffers; written only after __syncthreads when
// all walks are done): per warp k in {0,1,2} at S + k*NSLOT*32:
// 0..9 us | 10 csum | 11 cssum | 12 path | 13 fsum | 14 shsum | 15 dmsq | 16 uss
// 17 cossum | 18 cossq | 19 dirch | 20 maxdm | 21 negmn | 22 maxcs
// 23..32 vseg | 33..42 u_last | 43..52 d_first | 53 rin_first

__device__ __forceinline__ unsigned long long pk2(float a, float b) {
    unsigned long long r;
    asm("mov.b64 %0, {%1, %2};" : "=l"(r) : "f"(a), "f"(b));
    return r;
}
__device__ __forceinline__ void upk2(unsigned long long v, float& a, float& b) {
    asm("mov.b64 {%0, %1}, %2;" : "=f"(a), "=f"(b) : "l"(v));
}
__device__ __forceinline__ unsigned long long fma2(unsigned long long a,
                                                   unsigned long long b,
                                                   unsigned long long c) {
    unsigned long long d;
    asm("fma.rn.f32x2 %0, %1, %2, %3;" : "=l"(d) : "l"(a), "l"(b), "l"(c));
    return d;
}

// block = 128 threads = 4 warps splitting 32 trajectories' 48 rows (lane = traj)
__global__ void __launch_bounds__(128, 4)
fused_kernel(const float* __restrict__ coords, const int* __restrict__ lengths,
             const float* __restrict__ Wg, const float* __restrict__ bg,
             const float* __restrict__ lnwg, const float* __restrict__ lnbg,
             float* __restrict__ out, int B)
{
    __shared__ alignas(16) float S[SMEM_F];

    const int h    = threadIdx.x >> 5;      // warp: rows 12h .. 12h+12
    const int lane = threadIdx.x & 31;
    const int t0   = blockIdx.x * 32;
    if (t0 >= B) return;

    float* buf    = S + h * CHUNK_F;
    float* s_mini = S + OFF_MINI + h * 320;
    float* sfT    = S + OFF_FT;
    float* s_comb = S;                      // aliased on chunk buffers

    const int  traj = t0 + lane;
    const bool vt   = traj < B;
    const int  n    = vt ? __ldg(lengths + traj) : 4;
    const int  m    = n - 1;
    const int  half = m >> 1;
    const float nf  = (float)n;
    const float mf  = (float)m;
    const int  base = h * 12;

    float csum = 0.f, cssum = 0.f, path = 0.f, fsum = 0.f, shsum = 0.f;
    float dmsq = 0.f, uss = 0.f, cossum = 0.f, cossq = 0.f, dirch = 0.f;
    float maxdm = -F_INF, negmn = -F_INF, maxcs = -F_INF;
    float us[MD], prev[MD], dprev[MD], vseg[MD], dfs[MD], uls[MD];
#pragma unroll
    for (int k = 0; k < MD; k++) { us[k]=0.f; dprev[k]=0.f; vseg[k]=0.f; dfs[k]=0.f; uls[k]=0.f; }
    float rinprev = 0.f, rinfirst = 0.f;

    auto body = [&](int gr, const float* row) {
        if (gr != base) {
            float d[MD];
            float ssa = 0.f, ssb = 0.f;
#pragma unroll
            for (int k = 0; k < 5; k++)  { d[k] = row[k] - prev[k]; ssa = fmaf(d[k], d[k], ssa); }
#pragma unroll
            for (int k = 5; k < MD; k++) { d[k] = row[k] - prev[k]; ssb = fmaf(d[k], d[k], ssb); }
            float ss   = ssa + ssb;
            float ssc  = fmaxf(ss, 1e-30f);
            float rs   = rsqrtf(ssc);
            float dmag = (ss > 0.f) ? ssc * rs : 0.f;
            float rin  = (dmag > 1e-8f) ? rs : 1e8f;
            float dot  = 0.f;
#pragma unroll
            for (int k = 0; k < MD; k++) dot = fmaf(d[k], dprev[k], dot);
            float cosv = dot * rin * rinprev;
            const bool rv = gr < n;
            if (rv) {
                const int i = gr - 1;
                path += dmag;
                dmsq += ss;
                if (i <= half) fsum  += dmag;
                if (i >= half) shsum += dmag;
                maxdm = fmaxf(maxdm, dmag);
                uss   = fmaf(ss * rin, rin, uss);
#pragma unroll
                for (int k = 0; k < MD; k++) {
                    us[k]   = fmaf(d[k], rin, us[k]);
                    vseg[k] += d[k];
                }
                if (gr >= base + 2) {
                    cossum += cosv;
                    cossq   = fmaf(cosv, cosv, cossq);
                    negmn   = fmaxf(negmn, -cosv);
                    maxcs   = fmaxf(maxcs, cosv);
                    if (cosv < 0.f) dirch += 1.f;
                }
                if (i < 3) {       // only warp 0 reaches
#pragma unroll
                    for (int k = 0; k < MD; k++) sfT[(21 + i * MD + k) * 32 + lane] = d[k];
                }
            }
            if (gr >= 2 && gr <= 10)   // only warp 0 reaches
                sfT[(51 + gr - 2) * 32 + lane] = rv ? (1.f - cosv) : 0.f;
            if (gr == base + 1) {
#pragma unroll
                for (int k = 0; k < MD; k++) dfs[k] = d[k];
                rinfirst = rin;
            }
            if (gr == base + 12) {     // mini step (warps 0..2): last delta of segment
#pragma unroll
                for (int k = 0; k < MD; k++) uls[k] = d[k] * rin;
            }
#pragma unroll
            for (int k = 0; k < MD; k++) dprev[k] = d[k];
            rinprev = rin;
        }
        if (gr < n && (gr - base) < 12) {   // row ownership: 12 rows per warp
#pragma unroll
            for (int k = 0; k < MD; k++) { csum += row[k]; cssum = fmaf(row[k], row[k], cssum); }
        }
#pragma unroll
        for (int k = 0; k < MD; k++) prev[k] = row[k];
    };

    // ---- walk: 12 rows in 3 chunks of 4 (coalesced staging per warp) ----
    const float4* cb4 = (const float4*)coords;
    for (int c = 0; c < 3; c++) {
#pragma unroll
        for (int u = 0; u < 10; u++) {
            int j = u * 32 + lane, tt = j / 10, wi = j - tt * 10;
            int g = t0 + tt; if (g > B - 1) g = B - 1;
            float4 v = cb4[(size_t)g * 120 + h * 30 + c * 10 + wi];
            float* dst = buf + tt * CS + wi * 4;
            *(float2*)(dst)     = make_float2(v.x, v.y);
            *(float2*)(dst + 2) = make_float2(v.z, v.w);
        }
        __syncwarp();
#pragma unroll
        for (int r4 = 0; r4 < 4; r4++) {
            const int gr = base + c * 4 + r4;
            float row[MD];
            const float2* rp = (const float2*)(buf + lane * CS + r4 * MD);
#pragma unroll
            for (int k = 0; k < 5; k++) { float2 v = rp[k]; row[2*k] = v.x; row[2*k+1] = v.y; }
            body(gr, row);
        }
        __syncwarp();
    }

    // ---- warps 0..2: extra row 12h+12 (segment's last delta + boundary data) ----
    if (h < 3) {
#pragma unroll
        for (int u = 0; u < 5; u++) {
            int j = u * 32 + lane, tt = j / 5, wi = j - tt * 5;
            int g = t0 + tt; if (g > B - 1) g = B - 1;
            float2 v = ((const float2*)coords)[(size_t)g * 240 + h * 60 + 60 + wi];
            s_mini[tt * 10 + wi * 2]     = v.x;
            s_mini[tt * 10 + wi * 2 + 1] = v.y;
        }
        __syncwarp();
        float row[MD];
#pragma unroll
        for (int k = 0; k < MD; k++) row[k] = s_mini[lane * 10 + k];
        body(base + 12, row);
    }

    __syncthreads();    // ALL walks done -> chunk buffers dead -> comb alias safe

    if (h < 3) {
        float* cb = s_comb + h * NSLOT * 32;
#pragma unroll
        for (int k = 0; k < MD; k++) cb[k * 32 + lane] = us[k];
        cb[10*32+lane] = csum;   cb[11*32+lane] = cssum;
        cb[12*32+lane] = path;   cb[13*32+lane] = fsum;
        cb[14*32+lane] = shsum;  cb[15*32+lane] = dmsq;
        cb[16*32+lane] = uss;    cb[17*32+lane] = cossum;
        cb[18*32+lane] = cossq;  cb[19*32+lane] = dirch;
        cb[20*32+lane] = maxdm;  cb[21*32+lane] = negmn;
        cb[22*32+lane] = maxcs;
#pragma unroll
        for (int k = 0; k < MD; k++) {
            cb[(23 + k) * 32 + lane] = vseg[k];
            cb[(33 + k) * 32 + lane] = uls[k];
            cb[(43 + k) * 32 + lane] = dfs[k];
        }
        cb[53*32+lane] = rinfirst;
    }
    __syncthreads();

    // ---- warp 3 merges + epilogue ----
    if (h == 3) {
        float vtot[MD];
#pragma unroll
        for (int k = 0; k < MD; k++) vtot[k] = vseg[k];
#pragma unroll
        for (int w = 0; w < 3; w++) {
            const float* cb = s_comb + w * NSLOT * 32;
#pragma unroll
            for (int k = 0; k < MD; k++) us[k] += cb[k * 32 + lane];
            csum   += cb[10*32+lane];  cssum  += cb[11*32+lane];
            path   += cb[12*32+lane];  fsum   += cb[13*32+lane];
            shsum  += cb[14*32+lane];  dmsq   += cb[15*32+lane];
            uss    += cb[16*32+lane];  cossum += cb[17*32+lane];
            cossq  += cb[18*32+lane];  dirch  += cb[19*32+lane];
            maxdm = fmaxf(maxdm, cb[20*32+lane]);
            negmn = fmaxf(negmn, cb[21*32+lane]);
            maxcs = fmaxf(maxcs, cb[22*32+lane]);
#pragma unroll
            for (int k = 0; k < MD; k++) vtot[k] += cb[(23 + k) * 32 + lane];
        }

        // boundary cos terms b0,b1,b2 (indices 11,23,35; valid iff n >= 14/26/38)
#pragma unroll
        for (int bidx = 0; bidx < 3; bidx++) {
            const float* cbL = s_comb + bidx * NSLOT * 32;           // u_last of warp bidx
            float dot = 0.f, rf;
            if (bidx < 2) {
                const float* cbR = s_comb + (bidx + 1) * NSLOT * 32; // d_first of warp bidx+1
#pragma unroll
                for (int k = 0; k < MD; k++)
                    dot = fmaf(cbL[(33 + k) * 32 + lane], cbR[(43 + k) * 32 + lane], dot);
                rf = cbR[53*32+lane];
            } else {
#pragma unroll
                for (int k = 0; k < MD; k++)
                    dot = fmaf(cbL[(33 + k) * 32 + lane], dfs[k], dot);
                rf = rinfirst;
            }
            float cv = dot * rf;
            if (n >= 14 + 12 * bidx) {
                cossum += cv;
                cossq   = fmaf(cv, cv, cossq);
                negmn   = fmaxf(negmn, -cv);
                maxcs   = fmaxf(maxcs, cv);
                if (cv < 0.f) dirch += 1.f;
            }
        }

        float tdp = 0.f;
#pragma unroll
        for (int k = 0; k < MD; k++) tdp = fmaf(vtot[k], vtot[k], tdp);

        float s_mincs = -negmn;
        float total_disp = (tdp > 0.f) ? sqrtf(fmaxf(tdp, 1e-30f)) : 0.f;
        float disp_ratio = __fdividef(total_disp, path + F_EPS);
        float loop_score = 1.f - disp_ratio;
        float ncf  = (float)(n - 2);
        float rncf = __fdividef(1.f, ncf);
        float mean_cos  = cossum * rncf;
        float mean_curv = 1.f - mean_cos;
        float max_curv  = 1.0f - s_mincs;
        float cvsq      = ncf - 2.0f * cossum + cossq;
        float curv_var  = (cvsq - ncf * mean_curv * mean_curv)
                          * __fdividef(1.f, fmaxf(ncf - 1.f, 1.f));
        float std_curv  = (ncf > 1.f) ? sqrtf(fmaxf(curv_var, 1e-30f)) : 0.f;
        float curv_range = maxcs - s_mincs;
        float dir_chg   = dirch * rncf;
        float fh = fsum  * __fdividef(1.f, (float)(half + 1));
        float sh = shsum * __fdividef(1.f, (float)(m - half));
        float conv = __fdividef(fh - sh, fh + F_EPS);
        float nsq = 0.f;
#pragma unroll
        for (int k = 0; k < MD; k++) nsq = fmaf(us[k], us[k], nsq);
        float npairs = mf * (mf - 1.f) * 0.5f;
        float par = 0.5f * (nsq - uss) * __fdividef(1.f, fmaxf(npairs, 1.f));
        float mean_dm = path * __fdividef(1.f, mf);
        float dm_var  = (dmsq - mf * mean_dm * mean_dm)
                        * __fdividef(1.f, fmaxf(mf - 1.f, 1.f));
        float std_dm  = sqrtf(fmaxf(dm_var, 1e-30f));
        float jump = (mean_dm > F_EPS) ? __fdividef(maxdm, mean_dm) : 1.f;
        float cnt  = nf * (float)MD;
        float mc   = csum * __fdividef(1.f, cnt);
        float cvar = (cssum - cnt * mc * mc) * __fdividef(1.f, cnt - 1.f);
        float stdc = sqrtf(fmaxf(cvar, 1e-30f));

        sfT[ 0*32+lane] = total_disp;  sfT[ 1*32+lane] = path;
        sfT[ 2*32+lane] = disp_ratio;  sfT[ 3*32+lane] = nf * 0.1f;
        sfT[ 4*32+lane] = mean_curv;   sfT[ 5*32+lane] = max_curv;
        sfT[ 6*32+lane] = std_curv;    sfT[ 7*32+lane] = curv_range;
        sfT[ 8*32+lane] = mean_cos;    sfT[ 9*32+lane] = s_mincs;
        sfT[10*32+lane] = dir_chg;     sfT[11*32+lane] = disp_ratio;
        sfT[12*32+lane] = loop_score;  sfT[13*32+lane] = conv;
        sfT[14*32+lane] = par;         sfT[15*32+lane] = jump;
        sfT[16*32+lane] = -conv;       sfT[17*32+lane] = mean_dm;
        sfT[18*32+lane] = std_dm;      sfT[19*32+lane] = mc;
        sfT[20*32+lane] = stdc;
    }
    __syncthreads();

    // ---- GEMM + LN + GELU: warp h does rows h*8..h*8+7; lane = 2 rows x 6 cols ----
    {
        const int colg = lane & 7;
        const int rowq = lane >> 3;
        const int colb = colg * 6;
        const int rbase = h * 8 + rowq * 2;

        unsigned long long acc[2][3];
        {
            float2 bb0 = __ldg((const float2*)(bg + colb));
            float2 bb1 = __ldg((const float2*)(bg + colb + 2));
            float2 bb2 = __ldg((const float2*)(bg + colb + 4));
            unsigned long long b0 = pk2(bb0.x, bb0.y);
            unsigned long long b1 = pk2(bb1.x, bb1.y);
            unsigned long long b2 = pk2(bb2.x, bb2.y);
#pragma unroll
            for (int rr = 0; rr < 2; rr++) { acc[rr][0] = b0; acc[rr][1] = b1; acc[rr][2] = b2; }
        }

#pragma unroll 6
        for (int f = 0; f < NF; f++) {
            float2 wa = __ldg((const float2*)(Wg + f * H + colb));
            float2 wb = __ldg((const float2*)(Wg + f * H + colb + 2));
            float2 wc = __ldg((const float2*)(Wg + f * H + colb + 4));
            unsigned long long w0 = pk2(wa.x, wa.y);
            unsigned long long w1 = pk2(wb.x, wb.y);
            unsigned long long w2 = pk2(wc.x, wc.y);
            float2 fv = *(const float2*)(sfT + f * 32 + rbase);
            unsigned long long fp0 = pk2(fv.x, fv.x);
            unsigned long long fp1 = pk2(fv.y, fv.y);
            acc[0][0] = fma2(fp0, w0, acc[0][0]);
            acc[0][1] = fma2(fp0, w1, acc[0][1]);
            acc[0][2] = fma2(fp0, w2, acc[0][2]);
            acc[1][0] = fma2(fp1, w0, acc[1][0]);
            acc[1][1] = fma2(fp1, w1, acc[1][1]);
            acc[1][2] = fma2(fp1, w2, acc[1][2]);
        }

        float lw[6], lb[6];
        {
            float2 a0 = __ldg((const float2*)(lnwg + colb));
            float2 a1 = __ldg((const float2*)(lnwg + colb + 2));
            float2 a2 = __ldg((const float2*)(lnwg + colb + 4));
            float2 c0 = __ldg((const float2*)(lnbg + colb));
            float2 c1 = __ldg((const float2*)(lnbg + colb + 2));
            float2 c2 = __ldg((const float2*)(lnbg + colb + 4));
            lw[0]=a0.x; lw[1]=a0.y; lw[2]=a1.x; lw[3]=a1.y; lw[4]=a2.x; lw[5]=a2.y;
            lb[0]=c0.x; lb[1]=c0.y; lb[2]=c1.x; lb[3]=c1.y; lb[4]=c2.x; lb[5]=c2.y;
        }

#pragma unroll
        for (int rr = 0; rr < 2; rr++) {
            float x[6];
            upk2(acc[rr][0], x[0], x[1]);
            upk2(acc[rr][1], x[2], x[3]);
            upk2(acc[rr][2], x[4], x[5]);
            float s = 0.f, sq = 0.f;
#pragma unroll
            for (int c = 0; c < 6; c++) { s += x[c]; sq = fmaf(x[c], x[c], sq); }
#pragma unroll
            for (int o = 1; o < 8; o <<= 1) {
                s  += __shfl_xor_sync(FULLM, s,  o);
                sq += __shfl_xor_sync(FULLM, sq, o);
            }
            float mu  = s * (1.0f / 48.0f);
            float var = sq * (1.0f / 48.0f) - mu * mu;
            float inv = rsqrtf(var + 1e-5f);

            int trow = t0 + rbase + rr;
            if (trow < B) {
                float y[6];
#pragma unroll
                for (int c = 0; c < 6; c++) {
                    float v = (x[c] - mu) * inv * lw[c] + lb[c];
                    y[c] = v * normcdff(v);     // exact GELU
                }
                float* op = out + (size_t)trow * H + colb;
                *(float2*)(op + 0) = make_float2(y[0], y[1]);
                *(float2*)(op + 2) = make_float2(y[2], y[3]);
                *(float2*)(op + 4) = make_float2(y[4], y[5]);
            }
        }
    }
}

extern "C" void kernel_launch(void* const* d_in, const int* in_sizes, int n_in,
                              void* d_out, int out_size) {
    const float* coords  = (const float*)d_in[0];
    const int*   lengths = (const int*)d_in[1];
    const float* W       = (const float*)d_in[2];
    const float* b       = (const float*)d_in[3];
    const float* lnw     = (const float*)d_in[4];
    const float* lnb     = (const float*)d_in[5];
    float* out = (float*)d_out;

    int B = in_sizes[1];
    int grid = (B + 31) / 32;
    fused_kernel<<<grid, 128>>>(coords, lengths, W, b, lnw, lnb, out, B);
}